// round 6
// baseline (speedup 1.0000x reference)
#include <cuda_runtime.h>
#include <cstdint>

// image2patch: x[128,1,256,256] f32 -> out[128, 126*126, 36] f32
// out[b, pr*126+pc, kr*6+kc] = x[b, 0, 2*pr+kr, 2*pc+kc]
//
// v6: smem-staged shuffle + TMA bulk stores.
//  - block = (b, 6 patch rows). Stage 16 image rows (coalesced LDG.128).
//  - compute mapping: warp owns (q, 32 consecutive pc) -> LDS.64 gathers are
//    provably bank-conflict-free (16 lanes x stride-2 floats, single row).
//  - assembled float4 STS'd into an f-major staging chunk (conflict-free:
//    8 lanes/phase x stride-36 floats covers all 32 banks).
//  - one patch-row chunk = 1134 float4 = 18144B contiguous; issued as ONE
//    cp.async.bulk.global.shared::cta (TMA pipe, linear burst, evict_first),
//    double-buffered across the block's 6 chunks.

namespace {
constexpr int IMG     = 256;
constexpr int NPOS    = 126;
constexpr int PROWS   = 6;                 // patch-rows per block
constexpr int SROWS   = 16;                // image rows staged
constexpr int SROW    = IMG + 4;           // padded smem row stride (floats)
constexpr int THREADS = 512;
constexpr int CHUNK_F4    = NPOS * 9;      // 1134 float4 per patch-row
constexpr int CHUNK_BYTES = CHUNK_F4 * 16; // 18144
constexpr int SMEM_IN_FLOATS = SROWS * SROW;              // 4160
constexpr int SMEM_BYTES = SMEM_IN_FLOATS * 4 + 2 * CHUNK_BYTES;  // 52928
}

__device__ __forceinline__ uint32_t smem_u32(const void* p) {
    uint32_t a;
    asm("{ .reg .u64 t; cvta.to.shared.u64 t, %1; cvt.u32.u64 %0, t; }"
        : "=r"(a) : "l"(p));
    return a;
}

__global__ void __launch_bounds__(THREADS) image2patch_kernel(
    const float* __restrict__ x, float4* __restrict__ out)
{
    extern __shared__ float smem[];
    float*  s   = smem;                                        // input tile
    float4* stg = reinterpret_cast<float4*>(smem + SMEM_IN_FLOATS); // 2 chunks

    const int j   = blockIdx.x;            // 0..20
    const int b   = blockIdx.y;            // 0..127
    const int tid = threadIdx.x;
    const int wid  = tid >> 5;
    const int lane = tid & 31;

    const float* img = x + (size_t)b * (IMG * IMG);
    const int r0 = 12 * j;

    // --- stage 16 image rows, coalesced LDG.128 (exactly 2 full iters) ---
    #pragma unroll
    for (int it = 0; it < 2; ++it) {
        int i  = tid + it * THREADS;       // 0..1023
        int r  = i >> 6;
        int c4 = i & 63;
        float4 v = __ldg(reinterpret_cast<const float4*>(img + (r0 + r) * IMG) + c4);
        *reinterpret_cast<float4*>(&s[r * SROW + c4 * 4]) = v;
    }
    __syncthreads();

    const size_t outBase = ((size_t)b * NPOS + PROWS * j) * CHUNK_F4; // float4 units

    // L2 evict-first policy for the write stream (keep input resident)
    uint64_t pol;
    asm volatile("createpolicy.fractional.L2::evict_first.b64 %0, 1.0;" : "=l"(pol));

    #pragma unroll
    for (int c = 0; c < PROWS; ++c) {
        const int p = c & 1;

        // buffer p is being read by the bulk store issued at chunk c-2:
        // wait until at most 1 group still reading, then barrier.
        if (c >= 2 && tid == 0)
            asm volatile("cp.async.bulk.wait_group.read 1;" ::: "memory");
        __syncthreads();

        // --- compute chunk c (patch-row 6j+c) into stg[p] ---
        const int rb = 2 * c;
        float4* buf = stg + p * CHUNK_F4;

        #pragma unroll
        for (int t = wid; t < 36; t += 16) {   // task = (q, pc-group)
            int q  = t >> 2;                   // 0..8
            int g  = t & 3;                    // 0..3
            int pc = g * 32 + lane;
            if (pc < NPOS) {
                int e0 = 4 * q, e1 = e0 + 2;
                int kr0 = e0 / 6, kc0 = e0 - 6 * kr0;
                int kr1 = e1 / 6, kc1 = e1 - 6 * kr1;
                float2 a  = *reinterpret_cast<const float2*>(
                                &s[(rb + kr0) * SROW + 2 * pc + kc0]);
                float2 cc = *reinterpret_cast<const float2*>(
                                &s[(rb + kr1) * SROW + 2 * pc + kc1]);
                float4 v;
                v.x = a.x; v.y = a.y; v.z = cc.x; v.w = cc.y;
                buf[pc * 9 + q] = v;           // conflict-free STS.128
            }
        }
        __syncthreads();

        // --- issue one bulk store for the whole 18144B chunk ---
        if (tid == 0) {
            asm volatile("fence.proxy.async.shared::cta;" ::: "memory");
            uint32_t saddr = smem_u32(buf);
            void* gptr = (void*)(out + outBase + (size_t)c * CHUNK_F4);
            asm volatile(
                "cp.async.bulk.global.shared::cta.bulk_group.L2::cache_hint "
                "[%0], [%1], %2, %3;"
                :: "l"(gptr), "r"(saddr), "r"(CHUNK_BYTES), "l"(pol)
                : "memory");
            asm volatile("cp.async.bulk.commit_group;" ::: "memory");
        }
    }

    // drain all bulk stores before the block (and its smem) retires
    if (tid == 0)
        asm volatile("cp.async.bulk.wait_group 0;" ::: "memory");
    __syncthreads();
}

extern "C" void kernel_launch(void* const* d_in, const int* in_sizes, int n_in,
                              void* d_out, int out_size)
{
    const float* x = (const float*)d_in[0];
    float4* out = (float4*)d_out;

    cudaFuncSetAttribute(image2patch_kernel,
                         cudaFuncAttributeMaxDynamicSharedMemorySize, SMEM_BYTES);

    dim3 grid(NPOS / PROWS, 128);          // (21, 128)
    image2patch_kernel<<<grid, THREADS, SMEM_BYTES>>>(x, out);
}